// round 1
// baseline (speedup 1.0000x reference)
#include <cuda_runtime.h>
#include <math.h>

#define Nn   4096
#define Bb   2048
#define DIM  128
#define EPSV 1e-8f
#define INV_T 14.285714285714285714f   // 1/0.07

// ---------------- scratch (static device memory, no allocs) ----------------
__device__ float        g_z[Nn * DIM];                  // 2 MB normalized embeddings
__device__ float        g_sim[(size_t)Nn * Nn];         // 64 MB sim matrix
__device__ float        g_row[Nn];                      // per-row results
__device__ float        g_inv_dymax;
__device__ unsigned int g_min_key;                      // ordered-uint encoding of min(sim)

// monotone float<->uint mapping (ascending) for atomicMin
__device__ __forceinline__ unsigned fflip(float f) {
    unsigned u = __float_as_uint(f);
    return (u & 0x80000000u) ? ~u : (u | 0x80000000u);
}
__device__ __forceinline__ float funflip(unsigned k) {
    return __uint_as_float((k & 0x80000000u) ? (k & 0x7FFFFFFFu) : ~k);
}

// ---------------- kernel 1: labels min/max + init ----------------
__global__ void labels_kernel(const float* __restrict__ labels) {
    __shared__ float smn[32], smx[32];
    int tid = threadIdx.x;
    float mn = 1e30f, mx = -1e30f;
    for (int i = tid; i < Bb; i += 1024) {
        float v = labels[i];
        mn = fminf(mn, v);
        mx = fmaxf(mx, v);
    }
    #pragma unroll
    for (int off = 16; off; off >>= 1) {
        mn = fminf(mn, __shfl_xor_sync(0xffffffffu, mn, off));
        mx = fmaxf(mx, __shfl_xor_sync(0xffffffffu, mx, off));
    }
    int lane = tid & 31, w = tid >> 5;
    if (lane == 0) { smn[w] = mn; smx[w] = mx; }
    __syncthreads();
    if (tid == 0) {
        float a = smn[0], b = smx[0];
        for (int i = 1; i < 32; i++) { a = fminf(a, smn[i]); b = fmaxf(b, smx[i]); }
        g_inv_dymax = 1.0f / ((b - a) + EPSV);
        g_min_key   = 0xFFFFFFFFu;   // +inf under the ordered mapping
    }
}

// ---------------- kernel 2: normalize features -> g_z (view-major) ----------
__global__ void normalize_kernel(const float* __restrict__ feats) {
    int gw   = (blockIdx.x * blockDim.x + threadIdx.x) >> 5;   // one warp per row
    int lane = threadIdx.x & 31;
    if (gw >= Nn) return;
    int b = gw & (Bb - 1);
    int v = gw >> 11;
    const float* src = feats + ((size_t)b * 2 + v) * DIM;
    float4 x = *(const float4*)(src + lane * 4);
    float s = x.x * x.x + x.y * x.y + x.z * x.z + x.w * x.w;
    #pragma unroll
    for (int off = 16; off; off >>= 1) s += __shfl_xor_sync(0xffffffffu, s, off);
    float inv = 1.0f / fmaxf(sqrtf(s), 1e-12f);
    x.x *= inv; x.y *= inv; x.z *= inv; x.w *= inv;
    *(float4*)(g_z + (size_t)gw * DIM + lane * 4) = x;
}

// ---------------- kernel 3: sim = z z^T + global min(sim) ------------------
__global__ __launch_bounds__(256, 2) void gemm_min_kernel() {
    __shared__ float As[32][132];
    __shared__ float Bs[32][132];
    __shared__ float wmin[8];

    int tid = threadIdx.x;
    int i0 = blockIdx.y * 128;
    int j0 = blockIdx.x * 128;
    int tx = tid & 15, ty = tid >> 4;

    float acc[8][8];
    #pragma unroll
    for (int e = 0; e < 8; e++)
        #pragma unroll
        for (int f = 0; f < 8; f++) acc[e][f] = 0.0f;

    int r    = tid >> 1;
    int half = tid & 1;
    const float* zA = g_z + (size_t)(i0 + r) * DIM;
    const float* zB = g_z + (size_t)(j0 + r) * DIM;

    for (int kc = 0; kc < DIM; kc += 32) {
        __syncthreads();
        #pragma unroll
        for (int q = 0; q < 4; q++) {
            int c0 = half * 16 + q * 4;
            float4 va = *(const float4*)(zA + kc + c0);
            As[c0 + 0][r] = va.x; As[c0 + 1][r] = va.y;
            As[c0 + 2][r] = va.z; As[c0 + 3][r] = va.w;
            float4 vb = *(const float4*)(zB + kc + c0);
            Bs[c0 + 0][r] = vb.x; Bs[c0 + 1][r] = vb.y;
            Bs[c0 + 2][r] = vb.z; Bs[c0 + 3][r] = vb.w;
        }
        __syncthreads();
        #pragma unroll 4
        for (int kk = 0; kk < 32; kk++) {
            float a[8], b[8];
            *(float4*)&a[0] = *(const float4*)&As[kk][ty * 8];
            *(float4*)&a[4] = *(const float4*)&As[kk][ty * 8 + 4];
            *(float4*)&b[0] = *(const float4*)&Bs[kk][tx * 8];
            *(float4*)&b[4] = *(const float4*)&Bs[kk][tx * 8 + 4];
            #pragma unroll
            for (int e = 0; e < 8; e++)
                #pragma unroll
                for (int f = 0; f < 8; f++)
                    acc[e][f] = fmaf(a[e], b[f], acc[e][f]);
        }
    }

    float mn = 1e30f;
    #pragma unroll
    for (int e = 0; e < 8; e++) {
        int i = i0 + ty * 8 + e;
        float* outp = g_sim + (size_t)i * Nn + j0 + tx * 8;
        float4 o0 = make_float4(acc[e][0], acc[e][1], acc[e][2], acc[e][3]);
        float4 o1 = make_float4(acc[e][4], acc[e][5], acc[e][6], acc[e][7]);
        *(float4*)outp       = o0;
        *(float4*)(outp + 4) = o1;
        #pragma unroll
        for (int f = 0; f < 8; f++) mn = fminf(mn, acc[e][f]);
    }
    #pragma unroll
    for (int off = 16; off; off >>= 1) mn = fminf(mn, __shfl_down_sync(0xffffffffu, mn, off));
    if ((tid & 31) == 0) wmin[tid >> 5] = mn;
    __syncthreads();
    if (tid == 0) {
        float m2 = wmin[0];
        #pragma unroll
        for (int w = 1; w < 8; w++) m2 = fminf(m2, wmin[w]);
        atomicMin(&g_min_key, fflip(m2));
    }
}

// ---------------- kernel 4: per-row S1/S2/denom -> g_row --------------------
__global__ __launch_bounds__(256) void row_kernel(const float* __restrict__ labels) {
    __shared__ float ylab[Bb];
    __shared__ float red[3][8];
    int tid = threadIdx.x;
    for (int i = tid; i < Bb; i += 256) ylab[i] = labels[i];
    __syncthreads();

    int i = blockIdx.x;
    float inv_dz = 1.0f / ((1.0f - funflip(g_min_key)) + EPSV);
    float inv_dy = g_inv_dymax;
    float yi = ylab[i & (Bb - 1)];
    const float* rowp = g_sim + (size_t)i * Nn;

    float denom = 0.0f, s1 = 0.0f, s2 = 0.0f;
    #pragma unroll 4
    for (int j = tid; j < Nn; j += 256) {
        float s   = rowp[j];
        float t   = s * INV_T;
        float es  = __expf(t);
        float dy  = yi - ylab[j & (Bb - 1)];
        float w   = __expf(-2.0f * dy * dy);       // sigma=0.5 -> 1/(2s^2)=2
        w = fminf(fmaxf(w, 0.0f), 1.0f);
        float dya = fabsf(dy) * inv_dy;
        float dz  = (1.0f - s) * inv_dz;
        float u   = fminf(fmaxf(dz - dya, -1.0f), 1.0f);
        float wh  = 1.0f + fmaxf(-u, 0.0f) + w * u;  // == w*m + (1-w)*n
        if (j != i) {
            denom += es;
            s1    += wh;
            s2    += wh * wh * t;
        }
    }

    // block reductions (fixed tree -> deterministic)
    float vals[3] = {denom, s1, s2};
    int lane = tid & 31, w = tid >> 5;
    #pragma unroll
    for (int k = 0; k < 3; k++) {
        float v = vals[k];
        #pragma unroll
        for (int off = 16; off; off >>= 1) v += __shfl_xor_sync(0xffffffffu, v, off);
        if (lane == 0) red[k][w] = v;
    }
    __syncthreads();
    if (tid == 0) {
        float d = 0, a = 0, b = 0;
        #pragma unroll
        for (int x = 0; x < 8; x++) { d += red[0][x]; a += red[1][x]; b += red[2][x]; }
        d += EPSV;
        float L = logf(d);
        g_row[i] = (b - a * L) / (a + EPSV);
    }
}

// ---------------- kernel 5: final mean --------------------------------------
__global__ void final_kernel(float* __restrict__ out) {
    __shared__ float sm[32];
    int tid = threadIdx.x;
    float s = 0.0f;
    for (int i = tid; i < Nn; i += 1024) s += g_row[i];
    #pragma unroll
    for (int off = 16; off; off >>= 1) s += __shfl_xor_sync(0xffffffffu, s, off);
    int lane = tid & 31, w = tid >> 5;
    if (lane == 0) sm[w] = s;
    __syncthreads();
    if (tid == 0) {
        float t = 0.0f;
        #pragma unroll
        for (int x = 0; x < 32; x++) t += sm[x];
        out[0] = -(t / (float)Nn);
    }
}

// ---------------- launch ----------------------------------------------------
extern "C" void kernel_launch(void* const* d_in, const int* in_sizes, int n_in,
                              void* d_out, int out_size) {
    const float* feats  = (const float*)d_in[0];   // [2048, 2, 128] f32
    const float* labels = (const float*)d_in[1];   // [2048, 1] f32
    float* out = (float*)d_out;

    labels_kernel<<<1, 1024>>>(labels);
    normalize_kernel<<<512, 256>>>(feats);          // 4096 warps, 1 row each
    dim3 g(Nn / 128, Nn / 128);
    gemm_min_kernel<<<g, 256>>>();
    row_kernel<<<Nn, 256>>>(labels);
    final_kernel<<<1, 1024>>>(out);
}

// round 2
// speedup vs baseline: 1.3483x; 1.3483x over previous
#include <cuda_runtime.h>
#include <math.h>

#define Nn   4096
#define Bb   2048
#define DIM  128
#define EPSV 1e-8f
#define INV_T 14.285714285714285714f   // 1/0.07

// ---------------- scratch (static device memory, no allocs) ----------------
__device__ float        g_z[Nn * DIM];                  // 2 MB normalized embeddings
__device__ float        g_sim[(size_t)Nn * Nn];         // 64 MB sim matrix
__device__ float        g_row[Nn];                      // per-row results
__device__ float        g_inv_dymax;
__device__ unsigned int g_min_key;                      // ordered-uint encoding of min(sim)

// monotone float<->uint mapping (ascending) for atomicMin
__device__ __forceinline__ unsigned fflip(float f) {
    unsigned u = __float_as_uint(f);
    return (u & 0x80000000u) ? ~u : (u | 0x80000000u);
}
__device__ __forceinline__ float funflip(unsigned k) {
    return __uint_as_float((k & 0x80000000u) ? (k & 0x7FFFFFFFu) : ~k);
}

// ---------------- kernel 1: labels min/max + init ----------------
__global__ void labels_kernel(const float* __restrict__ labels) {
    __shared__ float smn[32], smx[32];
    int tid = threadIdx.x;
    float mn = 1e30f, mx = -1e30f;
    for (int i = tid; i < Bb; i += 1024) {
        float v = labels[i];
        mn = fminf(mn, v);
        mx = fmaxf(mx, v);
    }
    #pragma unroll
    for (int off = 16; off; off >>= 1) {
        mn = fminf(mn, __shfl_xor_sync(0xffffffffu, mn, off));
        mx = fmaxf(mx, __shfl_xor_sync(0xffffffffu, mx, off));
    }
    int lane = tid & 31, w = tid >> 5;
    if (lane == 0) { smn[w] = mn; smx[w] = mx; }
    __syncthreads();
    if (tid == 0) {
        float a = smn[0], b = smx[0];
        for (int i = 1; i < 32; i++) { a = fminf(a, smn[i]); b = fmaxf(b, smx[i]); }
        g_inv_dymax = 1.0f / ((b - a) + EPSV);
        g_min_key   = 0xFFFFFFFFu;   // +inf under the ordered mapping
    }
}

// ---------------- kernel 2: normalize features -> g_z (view-major) ----------
__global__ void normalize_kernel(const float* __restrict__ feats) {
    int gw   = (blockIdx.x * blockDim.x + threadIdx.x) >> 5;   // one warp per row
    int lane = threadIdx.x & 31;
    if (gw >= Nn) return;
    int b = gw & (Bb - 1);
    int v = gw >> 11;
    const float* src = feats + ((size_t)b * 2 + v) * DIM;
    float4 x = *(const float4*)(src + lane * 4);
    float s = x.x * x.x + x.y * x.y + x.z * x.z + x.w * x.w;
    #pragma unroll
    for (int off = 16; off; off >>= 1) s += __shfl_xor_sync(0xffffffffu, s, off);
    float inv = 1.0f / fmaxf(sqrtf(s), 1e-12f);
    x.x *= inv; x.y *= inv; x.z *= inv; x.w *= inv;
    *(float4*)(g_z + (size_t)gw * DIM + lane * 4) = x;
}

// ---------------- kernel 3: sim = z z^T (upper-tri tiles + mirror) ----------
// Grid (32, 32); blocks with by > bx exit (compute only j-tile >= i-tile).
// Mirror tile is bitwise identical because fmaf accumulation order over k is
// the same for (i,j) and (j,i).
__global__ __launch_bounds__(256, 2) void gemm_min_kernel() {
    int bx = blockIdx.x, by = blockIdx.y;
    if (by > bx) return;                 // keep j0 >= i0

    __shared__ float As[32][132];
    __shared__ float Bs[32][132];
    __shared__ float wmin[8];

    int tid = threadIdx.x;
    int i0 = by * 128;
    int j0 = bx * 128;
    int tx = tid & 15, ty = tid >> 4;

    float acc[8][8];
    #pragma unroll
    for (int e = 0; e < 8; e++)
        #pragma unroll
        for (int f = 0; f < 8; f++) acc[e][f] = 0.0f;

    int r    = tid >> 1;
    int half = tid & 1;
    const float* zA = g_z + (size_t)(i0 + r) * DIM;
    const float* zB = g_z + (size_t)(j0 + r) * DIM;

    for (int kc = 0; kc < DIM; kc += 32) {
        __syncthreads();
        #pragma unroll
        for (int q = 0; q < 4; q++) {
            int c0 = half * 16 + q * 4;
            float4 va = *(const float4*)(zA + kc + c0);
            As[c0 + 0][r] = va.x; As[c0 + 1][r] = va.y;
            As[c0 + 2][r] = va.z; As[c0 + 3][r] = va.w;
            float4 vb = *(const float4*)(zB + kc + c0);
            Bs[c0 + 0][r] = vb.x; Bs[c0 + 1][r] = vb.y;
            Bs[c0 + 2][r] = vb.z; Bs[c0 + 3][r] = vb.w;
        }
        __syncthreads();
        #pragma unroll 4
        for (int kk = 0; kk < 32; kk++) {
            float a[8], b[8];
            *(float4*)&a[0] = *(const float4*)&As[kk][ty * 8];
            *(float4*)&a[4] = *(const float4*)&As[kk][ty * 8 + 4];
            *(float4*)&b[0] = *(const float4*)&Bs[kk][tx * 8];
            *(float4*)&b[4] = *(const float4*)&Bs[kk][tx * 8 + 4];
            #pragma unroll
            for (int e = 0; e < 8; e++)
                #pragma unroll
                for (int f = 0; f < 8; f++)
                    acc[e][f] = fmaf(a[e], b[f], acc[e][f]);
        }
    }

    // normal store: rows i0+ty*8+e, cols j0+tx*8..+7
    float mn = 1e30f;
    #pragma unroll
    for (int e = 0; e < 8; e++) {
        int i = i0 + ty * 8 + e;
        float* outp = g_sim + (size_t)i * Nn + j0 + tx * 8;
        *(float4*)outp       = make_float4(acc[e][0], acc[e][1], acc[e][2], acc[e][3]);
        *(float4*)(outp + 4) = make_float4(acc[e][4], acc[e][5], acc[e][6], acc[e][7]);
        #pragma unroll
        for (int f = 0; f < 8; f++) mn = fminf(mn, acc[e][f]);
    }

    // mirror store (off-diagonal tiles only): rows j0+tx*8+f, cols i0+ty*8..+7
    if (bx != by) {
        #pragma unroll
        for (int f = 0; f < 8; f++) {
            int j = j0 + tx * 8 + f;
            float* outp = g_sim + (size_t)j * Nn + i0 + ty * 8;
            *(float4*)outp       = make_float4(acc[0][f], acc[1][f], acc[2][f], acc[3][f]);
            *(float4*)(outp + 4) = make_float4(acc[4][f], acc[5][f], acc[6][f], acc[7][f]);
        }
    }

    #pragma unroll
    for (int off = 16; off; off >>= 1) mn = fminf(mn, __shfl_down_sync(0xffffffffu, mn, off));
    if ((tid & 31) == 0) wmin[tid >> 5] = mn;
    __syncthreads();
    if (tid == 0) {
        float m2 = wmin[0];
        #pragma unroll
        for (int w = 1; w < 8; w++) m2 = fminf(m2, wmin[w]);
        atomicMin(&g_min_key, fflip(m2));
    }
}

// ---------------- kernel 4: per-row S1/S2/denom -> g_row --------------------
// Label terms repeat with period 2048 (two views): process (j, j+2048) pairs,
// sharing dy / w / dya.
__global__ __launch_bounds__(256) void row_kernel(const float* __restrict__ labels) {
    __shared__ float ylab[Bb];
    __shared__ float red[3][8];
    int tid = threadIdx.x;
    for (int i = tid; i < Bb; i += 256) ylab[i] = labels[i];
    __syncthreads();

    int i = blockIdx.x;
    float inv_dz = 1.0f / ((1.0f - funflip(g_min_key)) + EPSV);
    float inv_dy = g_inv_dymax;
    float yi = ylab[i & (Bb - 1)];
    const float* rowp = g_sim + (size_t)i * Nn;

    float denom = 0.0f, s1 = 0.0f, s2 = 0.0f;
    #pragma unroll 2
    for (int j = tid; j < Bb; j += 256) {
        float sa = rowp[j];
        float sb = rowp[j + Bb];
        float dy  = yi - ylab[j];
        float w   = fminf(__expf(-2.0f * dy * dy), 1.0f);   // sigma=0.5
        float dya = fabsf(dy) * inv_dy;

        float ta = sa * INV_T;
        float ea = __expf(ta);
        float ua = fminf(fmaxf((1.0f - sa) * inv_dz - dya, -1.0f), 1.0f);
        float wa = 1.0f + fmaxf(-ua, 0.0f) + w * ua;
        if (j != i) { denom += ea; s1 += wa; s2 += wa * wa * ta; }

        float tb = sb * INV_T;
        float eb = __expf(tb);
        float ub = fminf(fmaxf((1.0f - sb) * inv_dz - dya, -1.0f), 1.0f);
        float wb = 1.0f + fmaxf(-ub, 0.0f) + w * ub;
        if (j + Bb != i) { denom += eb; s1 += wb; s2 += wb * wb * tb; }
    }

    // block reductions (fixed tree -> deterministic)
    float vals[3] = {denom, s1, s2};
    int lane = tid & 31, w = tid >> 5;
    #pragma unroll
    for (int k = 0; k < 3; k++) {
        float v = vals[k];
        #pragma unroll
        for (int off = 16; off; off >>= 1) v += __shfl_xor_sync(0xffffffffu, v, off);
        if (lane == 0) red[k][w] = v;
    }
    __syncthreads();
    if (tid == 0) {
        float d = 0, a = 0, b = 0;
        #pragma unroll
        for (int x = 0; x < 8; x++) { d += red[0][x]; a += red[1][x]; b += red[2][x]; }
        d += EPSV;
        float L = logf(d);
        g_row[i] = (b - a * L) / (a + EPSV);
    }
}

// ---------------- kernel 5: final mean --------------------------------------
__global__ void final_kernel(float* __restrict__ out) {
    __shared__ float sm[32];
    int tid = threadIdx.x;
    float s = 0.0f;
    for (int i = tid; i < Nn; i += 1024) s += g_row[i];
    #pragma unroll
    for (int off = 16; off; off >>= 1) s += __shfl_xor_sync(0xffffffffu, s, off);
    int lane = tid & 31, w = tid >> 5;
    if (lane == 0) sm[w] = s;
    __syncthreads();
    if (tid == 0) {
        float t = 0.0f;
        #pragma unroll
        for (int x = 0; x < 32; x++) t += sm[x];
        out[0] = -(t / (float)Nn);
    }
}

// ---------------- launch ----------------------------------------------------
extern "C" void kernel_launch(void* const* d_in, const int* in_sizes, int n_in,
                              void* d_out, int out_size) {
    const float* feats  = (const float*)d_in[0];   // [2048, 2, 128] f32
    const float* labels = (const float*)d_in[1];   // [2048, 1] f32
    float* out = (float*)d_out;

    labels_kernel<<<1, 1024>>>(labels);
    normalize_kernel<<<512, 256>>>(feats);          // 4096 warps, 1 row each
    dim3 g(Nn / 128, Nn / 128);
    gemm_min_kernel<<<g, 256>>>();
    row_kernel<<<Nn, 256>>>(labels);
    final_kernel<<<1, 1024>>>(out);
}

// round 4
// speedup vs baseline: 1.8614x; 1.3805x over previous
#include <cuda_runtime.h>
#include <cuda_bf16.h>
#include <math.h>
#include <stdint.h>

#define Nn   4096
#define Bb   2048
#define DIM  128
#define NT   32
#define EPSV 1e-8f
#define INV_T 14.285714285714285714f   // 1/0.07

// ---------------- static device scratch ----------------
__device__ __nv_bfloat16 g_zh[Nn * DIM];       // 1 MB hi split
__device__ __nv_bfloat16 g_zl[Nn * DIM];       // 1 MB lo split
__device__ float         g_sim[(size_t)Nn * Nn];  // 64 MB sim matrix
__device__ float         g_row[Nn];
__device__ float         g_inv_dymax;
__device__ unsigned      g_min_key;

// panel layout in dynamic smem (bf16, 128 rows x 136 stride = 272 B/row)
#define PSTRIDE_B 272
#define PANEL_B   34816
#define OFF_AH 0
#define OFF_AL 34816
#define OFF_BH 69632
#define OFF_BL 104448
#define SMEM_A_BYTES 139264

__device__ __forceinline__ unsigned fflip(float f) {
    unsigned u = __float_as_uint(f);
    return (u & 0x80000000u) ? ~u : (u | 0x80000000u);
}
__device__ __forceinline__ float funflip(unsigned k) {
    return __uint_as_float((k & 0x80000000u) ? (k & 0x7FFFFFFFu) : ~k);
}
__device__ __forceinline__ uint32_t smem_u32(const void* p) {
    uint32_t a;
    asm("{ .reg .u64 t; cvta.to.shared.u64 t, %1; cvt.u32.u64 %0, t; }" : "=r"(a) : "l"(p));
    return a;
}
__device__ __forceinline__ void ldsm4(uint32_t& r0, uint32_t& r1, uint32_t& r2, uint32_t& r3, uint32_t a) {
    asm volatile("ldmatrix.sync.aligned.m8n8.x4.shared.b16 {%0,%1,%2,%3}, [%4];"
                 : "=r"(r0), "=r"(r1), "=r"(r2), "=r"(r3) : "r"(a));
}
__device__ __forceinline__ void mma16816(float* c, const uint32_t* a, const uint32_t* b) {
    asm volatile("mma.sync.aligned.m16n8k16.row.col.f32.bf16.bf16.f32 "
                 "{%0,%1,%2,%3},{%4,%5,%6,%7},{%8,%9},{%0,%1,%2,%3};"
                 : "+f"(c[0]), "+f"(c[1]), "+f"(c[2]), "+f"(c[3])
                 : "r"(a[0]), "r"(a[1]), "r"(a[2]), "r"(a[3]), "r"(b[0]), "r"(b[1]));
}

// ---------------- kernel 1: labels min/max + init ----------------
__global__ void labels_kernel(const float* __restrict__ labels) {
    __shared__ float smn[32], smx[32];
    int tid = threadIdx.x;
    float mn = 1e30f, mx = -1e30f;
    for (int i = tid; i < Bb; i += 1024) {
        float v = labels[i];
        mn = fminf(mn, v); mx = fmaxf(mx, v);
    }
    #pragma unroll
    for (int off = 16; off; off >>= 1) {
        mn = fminf(mn, __shfl_xor_sync(0xffffffffu, mn, off));
        mx = fmaxf(mx, __shfl_xor_sync(0xffffffffu, mx, off));
    }
    int lane = tid & 31, w = tid >> 5;
    if (lane == 0) { smn[w] = mn; smx[w] = mx; }
    __syncthreads();
    if (tid == 0) {
        float a = smn[0], b = smx[0];
        for (int i = 1; i < 32; i++) { a = fminf(a, smn[i]); b = fmaxf(b, smx[i]); }
        g_inv_dymax = 1.0f / ((b - a) + EPSV);
        g_min_key   = 0xFFFFFFFFu;
    }
}

// ---------------- kernel 2: normalize + bf16 split ----------------
__global__ void normalize_kernel(const float* __restrict__ feats) {
    int gw   = (blockIdx.x * blockDim.x + threadIdx.x) >> 5;
    int lane = threadIdx.x & 31;
    if (gw >= Nn) return;
    int b = gw & (Bb - 1);
    int v = gw >> 11;
    const float* src = feats + ((size_t)b * 2 + v) * DIM;
    float4 x = *(const float4*)(src + lane * 4);
    float s = x.x * x.x + x.y * x.y + x.z * x.z + x.w * x.w;
    #pragma unroll
    for (int off = 16; off; off >>= 1) s += __shfl_xor_sync(0xffffffffu, s, off);
    float inv = 1.0f / fmaxf(sqrtf(s), 1e-12f);
    float f0 = x.x * inv, f1 = x.y * inv, f2 = x.z * inv, f3 = x.w * inv;
    __nv_bfloat16 h0 = __float2bfloat16(f0), h1 = __float2bfloat16(f1);
    __nv_bfloat16 h2 = __float2bfloat16(f2), h3 = __float2bfloat16(f3);
    __nv_bfloat16 l0 = __float2bfloat16(f0 - __bfloat162float(h0));
    __nv_bfloat16 l1 = __float2bfloat16(f1 - __bfloat162float(h1));
    __nv_bfloat16 l2 = __float2bfloat16(f2 - __bfloat162float(h2));
    __nv_bfloat16 l3 = __float2bfloat16(f3 - __bfloat162float(h3));
    size_t base = (size_t)gw * DIM + lane * 4;
    *(__nv_bfloat162*)(g_zh + base)     = __halves2bfloat162(h0, h1);
    *(__nv_bfloat162*)(g_zh + base + 2) = __halves2bfloat162(h2, h3);
    *(__nv_bfloat162*)(g_zl + base)     = __halves2bfloat162(l0, l1);
    *(__nv_bfloat162*)(g_zl + base + 2) = __halves2bfloat162(l2, l3);
}

// ---------------- kernel 3: upper-tri tile GEMM (mma.sync bf16 3-pass) ------
// C = Ah*Bh^T + Ah*Bl^T + Al*Bh^T, fused min reduction + mirrored stores.
__global__ void __launch_bounds__(256, 1) simgen_kernel() {
    int bx = blockIdx.x, by = blockIdx.y;
    if (by > bx) return;
    extern __shared__ char sm[];
    __shared__ float wmin[8];
    uint32_t sb = smem_u32(sm);
    int tid = threadIdx.x, wid = tid >> 5, lane = tid & 31;
    int wm = wid & 3, wn = wid >> 2;

    // ---- load panels (row-major bf16, stride 136 elems) ----
    int r0 = by * 128, c0 = bx * 128;
    #pragma unroll
    for (int idx = tid; idx < 2048; idx += 256) {
        int row = idx >> 4, ch = idx & 15;       // 16B chunk = 8 bf16
        size_t gA = (size_t)(r0 + row) * DIM + ch * 8;
        size_t gB = (size_t)(c0 + row) * DIM + ch * 8;
        uint32_t so = (uint32_t)row * PSTRIDE_B + ch * 16;
        *(uint4*)(sm + OFF_AH + so) = *(const uint4*)(g_zh + gA);
        *(uint4*)(sm + OFF_AL + so) = *(const uint4*)(g_zl + gA);
        *(uint4*)(sm + OFF_BH + so) = *(const uint4*)(g_zh + gB);
        *(uint4*)(sm + OFF_BL + so) = *(const uint4*)(g_zl + gB);
    }
    __syncthreads();

    float c[2][8][4];
    #pragma unroll
    for (int im = 0; im < 2; im++)
        #pragma unroll
        for (int in = 0; in < 8; in++)
            #pragma unroll
            for (int r = 0; r < 4; r++) c[im][in][r] = 0.0f;

    // ldmatrix lane-address components
    int a_row  = ((lane >> 3) & 1) * 8 + (lane & 7);   // + im*16 + wm*32
    int a_koff = (lane >> 4) * 8;                       // 0 or 8 (k half)
    int b_row  = ((lane >> 4) & 1) * 8 + (lane & 7);   // + p*16 + wn*64
    int b_koff = ((lane >> 3) & 1) * 8;

    #pragma unroll
    for (int kc = 0; kc < 8; kc++) {
        uint32_t ah[2][4], al[2][4], bh[8][2], bl[8][2];
        #pragma unroll
        for (int im = 0; im < 2; im++) {
            uint32_t off = (uint32_t)(wm * 32 + im * 16 + a_row) * PSTRIDE_B
                         + (kc * 16 + a_koff) * 2;
            ldsm4(ah[im][0], ah[im][1], ah[im][2], ah[im][3], sb + OFF_AH + off);
            ldsm4(al[im][0], al[im][1], al[im][2], al[im][3], sb + OFF_AL + off);
        }
        #pragma unroll
        for (int p = 0; p < 4; p++) {
            uint32_t off = (uint32_t)(wn * 64 + p * 16 + b_row) * PSTRIDE_B
                         + (kc * 16 + b_koff) * 2;
            ldsm4(bh[2*p][0], bh[2*p][1], bh[2*p+1][0], bh[2*p+1][1], sb + OFF_BH + off);
            ldsm4(bl[2*p][0], bl[2*p][1], bl[2*p+1][0], bl[2*p+1][1], sb + OFF_BL + off);
        }
        #pragma unroll
        for (int im = 0; im < 2; im++)
            #pragma unroll
            for (int in = 0; in < 8; in++) {
                mma16816(c[im][in], ah[im], bh[in]);
                mma16816(c[im][in], ah[im], bl[in]);
                mma16816(c[im][in], al[im], bh[in]);
            }
    }

    // ---- min reduction ----
    float mn = 1e30f;
    #pragma unroll
    for (int im = 0; im < 2; im++)
        #pragma unroll
        for (int in = 0; in < 8; in++)
            #pragma unroll
            for (int r = 0; r < 4; r++) mn = fminf(mn, c[im][in][r]);
    #pragma unroll
    for (int off = 16; off; off >>= 1) mn = fminf(mn, __shfl_xor_sync(0xffffffffu, mn, off));
    if (lane == 0) wmin[wid] = mn;

    // ---- stage tile to smem fp32 (stride 132) for coalesced stores ----
    __syncthreads();             // panels dead; wmin written
    if (tid == 0) {
        float m = wmin[0];
        #pragma unroll
        for (int w = 1; w < 8; w++) m = fminf(m, wmin[w]);
        atomicMin(&g_min_key, fflip(m));
    }
    float* stile = (float*)sm;   // 128*132*4 = 67584 B <= 139264
    int tr = lane >> 2, tc = (lane & 3) * 2;
    #pragma unroll
    for (int im = 0; im < 2; im++)
        #pragma unroll
        for (int in = 0; in < 8; in++) {
            int rl = wm * 32 + im * 16 + tr;
            int cl = wn * 64 + in * 8 + tc;
            *(float2*)(stile + rl * 132 + cl)       = make_float2(c[im][in][0], c[im][in][1]);
            *(float2*)(stile + (rl + 8) * 132 + cl) = make_float2(c[im][in][2], c[im][in][3]);
        }
    __syncthreads();

    // normal store: g_sim[r0+ir][c0+jc], coalesced float4
    {
        int ir = tid >> 1, jc0 = (tid & 1) * 64;
        float* dst = g_sim + (size_t)(r0 + ir) * Nn + c0 + jc0;
        const float* srcr = stile + ir * 132 + jc0;
        #pragma unroll
        for (int q = 0; q < 16; q++)
            *(float4*)(dst + q * 4) = *(const float4*)(srcr + q * 4);
    }
    // mirror store (off-diagonal): g_sim[c0+jr][r0+ic], transposed read from smem
    if (bx != by) {
        int jr = tid >> 1, ic0 = (tid & 1) * 64;
        float* dst = g_sim + (size_t)(c0 + jr) * Nn + r0 + ic0;
        #pragma unroll
        for (int q = 0; q < 16; q++) {
            int ic = ic0 + q * 4;
            float4 v;
            v.x = stile[(ic + 0) * 132 + jr];
            v.y = stile[(ic + 1) * 132 + jr];
            v.z = stile[(ic + 2) * 132 + jr];
            v.w = stile[(ic + 3) * 132 + jr];
            *(float4*)dst = v;
            dst += 4;
        }
    }
}

// ---------------- kernel 4: per-row pass -> g_row ----------------
__global__ void __launch_bounds__(256) void_dummy(); // (unused fwd decl guard)
__global__ void __launch_bounds__(256) rowpass_kernel(const float* __restrict__ labels) {
    __shared__ float ylab[Bb];
    __shared__ float red[3][8];
    int tid = threadIdx.x;
    for (int j = tid; j < Bb; j += 256) ylab[j] = labels[j];
    __syncthreads();

    int i = blockIdx.x;
    float inv_dz = 1.0f / ((1.0f - funflip(g_min_key)) + EPSV);
    float inv_dy = g_inv_dymax;
    float yi = ylab[i & (Bb - 1)];
    const float* rowp = g_sim + (size_t)i * Nn;

    float denom = 0.0f, s1 = 0.0f, s2 = 0.0f;
    #pragma unroll
    for (int base = 0; base < Bb; base += 1024) {
        int j0 = base + tid * 4;
        float4 sa = *(const float4*)(rowp + j0);
        float4 sb = *(const float4*)(rowp + j0 + Bb);
        float se[8] = {sa.x, sa.y, sa.z, sa.w, sb.x, sb.y, sb.z, sb.w};
        #pragma unroll
        for (int e = 0; e < 4; e++) {
            float dy = yi - ylab[j0 + e];
            float w  = __expf(-2.0f * dy * dy);            // in [0,1] by construction
            float h  = inv_dz - fabsf(dy) * inv_dy;        // u = h - s*inv_dz
            #pragma unroll
            for (int v = 0; v < 2; v++) {
                float s  = se[e + v * 4];
                float t  = s * INV_T;
                float es = __expf(t);
                float u  = fminf(fmaxf(fmaf(-inv_dz, s, h), -1.0f), 1.0f);
                float wh = fmaf(w, u, 1.0f + fmaxf(-u, 0.0f));
                denom += es;
                s1    += wh;
                s2     = fmaf(wh * wh, t, s2);
            }
        }
    }

    float vals[3] = {denom, s1, s2};
    int lane = tid & 31, w = tid >> 5;
    #pragma unroll
    for (int k = 0; k < 3; k++) {
        float v = vals[k];
        #pragma unroll
        for (int off = 16; off; off >>= 1) v += __shfl_xor_sync(0xffffffffu, v, off);
        if (lane == 0) red[k][w] = v;
    }
    __syncthreads();
    if (tid == 0) {
        float d = 0, a = 0, b = 0;
        #pragma unroll
        for (int x = 0; x < 8; x++) { d += red[0][x]; a += red[1][x]; b += red[2][x]; }
        // subtract diagonal term (j == i), which the loop included
        float sdv = rowp[i];
        float td  = sdv * INV_T;
        float esd = __expf(td);
        float ud  = fminf(fmaxf((1.0f - sdv) * inv_dz, -1.0f), 1.0f);
        float whd = 1.0f + fmaxf(ud, 0.0f);    // w=1: 1 + relu(u)
        d -= esd; a -= whd; b -= whd * whd * td;
        d += EPSV;
        float L = logf(d);
        g_row[i] = (b - a * L) / (a + EPSV);
    }
}

// ---------------- kernel 5: final mean ----------------
__global__ void final_kernel(float* __restrict__ out) {
    __shared__ float smem[32];
    int tid = threadIdx.x;
    float s = 0.0f;
    for (int i = tid; i < Nn; i += 1024) s += g_row[i];
    #pragma unroll
    for (int off = 16; off; off >>= 1) s += __shfl_xor_sync(0xffffffffu, s, off);
    int lane = tid & 31, w = tid >> 5;
    if (lane == 0) smem[w] = s;
    __syncthreads();
    if (tid == 0) {
        float t = 0.0f;
        #pragma unroll
        for (int x = 0; x < 32; x++) t += smem[x];
        out[0] = -(t / (float)Nn);
    }
}

// ---------------- launch ----------------
extern "C" void kernel_launch(void* const* d_in, const int* in_sizes, int n_in,
                              void* d_out, int out_size) {
    const float* feats  = (const float*)d_in[0];
    const float* labels = (const float*)d_in[1];
    float* out = (float*)d_out;

    cudaFuncSetAttribute(simgen_kernel, cudaFuncAttributeMaxDynamicSharedMemorySize, SMEM_A_BYTES);

    labels_kernel<<<1, 1024>>>(labels);
    normalize_kernel<<<512, 256>>>(feats);
    dim3 g(NT, NT);
    simgen_kernel<<<g, 256, SMEM_A_BYTES>>>();
    rowpass_kernel<<<Nn, 256>>>(labels);
    final_kernel<<<1, 1024>>>(out);
}

// round 5
// speedup vs baseline: 1.9645x; 1.0554x over previous
#include <cuda_runtime.h>
#include <cuda_bf16.h>
#include <math.h>
#include <stdint.h>

#define Nn   4096
#define Bb   2048
#define DIM  128
#define NT   32
#define EPSV 1e-8f
#define INV_T 14.285714285714285714f   // 1/0.07

// ---------------- static device scratch ----------------
__device__ __nv_bfloat16 g_zh[Nn * DIM];      // 1 MB hi split
__device__ __nv_bfloat16 g_zl[Nn * DIM];      // 1 MB lo split
__device__ float         g_pdr[3][NT][Nn];    // row-side partials (slot = bx)
__device__ float         g_pdc[3][NT][Nn];    // col-side partials (slot = by)
__device__ float         g_row[Nn];
__device__ float         g_inv_dymax;
__device__ unsigned      g_min_key;

// panel layout in dynamic smem (bf16, 128 rows x 136 stride = 272 B/row)
#define PSTRIDE_B 272
#define OFF_AH 0
#define OFF_AL 34816
#define OFF_BH 69632
#define OFF_BL 104448
#define PANEL_BYTES 139264

__device__ __forceinline__ unsigned fflip(float f) {
    unsigned u = __float_as_uint(f);
    return (u & 0x80000000u) ? ~u : (u | 0x80000000u);
}
__device__ __forceinline__ float funflip(unsigned k) {
    return __uint_as_float((k & 0x80000000u) ? (k & 0x7FFFFFFFu) : ~k);
}
__device__ __forceinline__ uint32_t smem_u32(const void* p) {
    uint32_t a;
    asm("{ .reg .u64 t; cvta.to.shared.u64 t, %1; cvt.u32.u64 %0, t; }" : "=r"(a) : "l"(p));
    return a;
}
__device__ __forceinline__ void ldsm4(uint32_t& r0, uint32_t& r1, uint32_t& r2, uint32_t& r3, uint32_t a) {
    asm volatile("ldmatrix.sync.aligned.m8n8.x4.shared.b16 {%0,%1,%2,%3}, [%4];"
                 : "=r"(r0), "=r"(r1), "=r"(r2), "=r"(r3) : "r"(a));
}
__device__ __forceinline__ void mma16816(float* c, const uint32_t* a, const uint32_t* b) {
    asm volatile("mma.sync.aligned.m16n8k16.row.col.f32.bf16.bf16.f32 "
                 "{%0,%1,%2,%3},{%4,%5,%6,%7},{%8,%9},{%0,%1,%2,%3};"
                 : "+f"(c[0]), "+f"(c[1]), "+f"(c[2]), "+f"(c[3])
                 : "r"(a[0]), "r"(a[1]), "r"(a[2]), "r"(a[3]), "r"(b[0]), "r"(b[1]));
}

// ---------------- shared GEMM tile body (3-pass bf16 split) ----------------
__device__ __forceinline__ void gemm_tile_mma(char* sm, uint32_t sb, int by, int bx,
                                              int tid, int wid, int lane,
                                              float c[2][8][4]) {
    int wm = wid & 3, wn = wid >> 2;
    int r0 = by * 128, c0 = bx * 128;
    #pragma unroll
    for (int idx = tid; idx < 2048; idx += 256) {
        int row = idx >> 4, ch = idx & 15;
        size_t gA = (size_t)(r0 + row) * DIM + ch * 8;
        size_t gB = (size_t)(c0 + row) * DIM + ch * 8;
        uint32_t so = (uint32_t)row * PSTRIDE_B + ch * 16;
        *(uint4*)(sm + OFF_AH + so) = *(const uint4*)(g_zh + gA);
        *(uint4*)(sm + OFF_AL + so) = *(const uint4*)(g_zl + gA);
        *(uint4*)(sm + OFF_BH + so) = *(const uint4*)(g_zh + gB);
        *(uint4*)(sm + OFF_BL + so) = *(const uint4*)(g_zl + gB);
    }
    __syncthreads();

    #pragma unroll
    for (int im = 0; im < 2; im++)
        #pragma unroll
        for (int in = 0; in < 8; in++)
            #pragma unroll
            for (int r = 0; r < 4; r++) c[im][in][r] = 0.0f;

    int a_row  = ((lane >> 3) & 1) * 8 + (lane & 7);
    int a_koff = (lane >> 4) * 8;
    int b_row  = ((lane >> 4) & 1) * 8 + (lane & 7);
    int b_koff = ((lane >> 3) & 1) * 8;

    #pragma unroll
    for (int kc = 0; kc < 8; kc++) {
        uint32_t ah[2][4], al[2][4], bh[8][2], bl[8][2];
        #pragma unroll
        for (int im = 0; im < 2; im++) {
            uint32_t off = (uint32_t)(wm * 32 + im * 16 + a_row) * PSTRIDE_B
                         + (kc * 16 + a_koff) * 2;
            ldsm4(ah[im][0], ah[im][1], ah[im][2], ah[im][3], sb + OFF_AH + off);
            ldsm4(al[im][0], al[im][1], al[im][2], al[im][3], sb + OFF_AL + off);
        }
        #pragma unroll
        for (int p = 0; p < 4; p++) {
            uint32_t off = (uint32_t)(wn * 64 + p * 16 + b_row) * PSTRIDE_B
                         + (kc * 16 + b_koff) * 2;
            ldsm4(bh[2*p][0], bh[2*p][1], bh[2*p+1][0], bh[2*p+1][1], sb + OFF_BH + off);
            ldsm4(bl[2*p][0], bl[2*p][1], bl[2*p+1][0], bl[2*p+1][1], sb + OFF_BL + off);
        }
        #pragma unroll
        for (int im = 0; im < 2; im++)
            #pragma unroll
            for (int in = 0; in < 8; in++) {
                mma16816(c[im][in], ah[im], bh[in]);
                mma16816(c[im][in], ah[im], bl[in]);
                mma16816(c[im][in], al[im], bh[in]);
            }
    }
}

// ---------------- kernel 1: labels min/max + init ----------------
__global__ void labels_kernel(const float* __restrict__ labels) {
    __shared__ float smn[32], smx[32];
    int tid = threadIdx.x;
    float mn = 1e30f, mx = -1e30f;
    for (int i = tid; i < Bb; i += 1024) {
        float v = labels[i];
        mn = fminf(mn, v); mx = fmaxf(mx, v);
    }
    #pragma unroll
    for (int off = 16; off; off >>= 1) {
        mn = fminf(mn, __shfl_xor_sync(0xffffffffu, mn, off));
        mx = fmaxf(mx, __shfl_xor_sync(0xffffffffu, mx, off));
    }
    int lane = tid & 31, w = tid >> 5;
    if (lane == 0) { smn[w] = mn; smx[w] = mx; }
    __syncthreads();
    if (tid == 0) {
        float a = smn[0], b = smx[0];
        for (int i = 1; i < 32; i++) { a = fminf(a, smn[i]); b = fmaxf(b, smx[i]); }
        g_inv_dymax = 1.0f / ((b - a) + EPSV);
        g_min_key   = 0xFFFFFFFFu;
    }
}

// ---------------- kernel 2: normalize + bf16 split ----------------
__global__ void normalize_kernel(const float* __restrict__ feats) {
    int gw   = (blockIdx.x * blockDim.x + threadIdx.x) >> 5;
    int lane = threadIdx.x & 31;
    if (gw >= Nn) return;
    int b = gw & (Bb - 1);
    int v = gw >> 11;
    const float* src = feats + ((size_t)b * 2 + v) * DIM;
    float4 x = *(const float4*)(src + lane * 4);
    float s = x.x * x.x + x.y * x.y + x.z * x.z + x.w * x.w;
    #pragma unroll
    for (int off = 16; off; off >>= 1) s += __shfl_xor_sync(0xffffffffu, s, off);
    float inv = 1.0f / fmaxf(sqrtf(s), 1e-12f);
    float f0 = x.x * inv, f1 = x.y * inv, f2 = x.z * inv, f3 = x.w * inv;
    __nv_bfloat16 h0 = __float2bfloat16(f0), h1 = __float2bfloat16(f1);
    __nv_bfloat16 h2 = __float2bfloat16(f2), h3 = __float2bfloat16(f3);
    __nv_bfloat16 l0 = __float2bfloat16(f0 - __bfloat162float(h0));
    __nv_bfloat16 l1 = __float2bfloat16(f1 - __bfloat162float(h1));
    __nv_bfloat16 l2 = __float2bfloat16(f2 - __bfloat162float(h2));
    __nv_bfloat16 l3 = __float2bfloat16(f3 - __bfloat162float(h3));
    size_t base = (size_t)gw * DIM + lane * 4;
    *(__nv_bfloat162*)(g_zh + base)     = __halves2bfloat162(h0, h1);
    *(__nv_bfloat162*)(g_zh + base + 2) = __halves2bfloat162(h2, h3);
    *(__nv_bfloat162*)(g_zl + base)     = __halves2bfloat162(l0, l1);
    *(__nv_bfloat162*)(g_zl + base + 2) = __halves2bfloat162(l2, l3);
}

// ---------------- kernel 3: min pass (upper tiles, no stores) ----------------
__global__ void __launch_bounds__(256, 1) minpass_kernel() {
    int bx = blockIdx.x, by = blockIdx.y;
    if (by > bx) return;
    extern __shared__ char sm[];
    __shared__ float wmin[8];
    uint32_t sb = smem_u32(sm);
    int tid = threadIdx.x, wid = tid >> 5, lane = tid & 31;

    float c[2][8][4];
    gemm_tile_mma(sm, sb, by, bx, tid, wid, lane, c);

    float mn = 1e30f;
    #pragma unroll
    for (int im = 0; im < 2; im++)
        #pragma unroll
        for (int in = 0; in < 8; in++)
            #pragma unroll
            for (int r = 0; r < 4; r++) mn = fminf(mn, c[im][in][r]);
    #pragma unroll
    for (int off = 16; off; off >>= 1) mn = fminf(mn, __shfl_xor_sync(0xffffffffu, mn, off));
    if (lane == 0) wmin[wid] = mn;
    __syncthreads();
    if (tid == 0) {
        float m = wmin[0];
        #pragma unroll
        for (int w = 1; w < 8; w++) m = fminf(m, wmin[w]);
        atomicMin(&g_min_key, fflip(m));
    }
}

// ---------------- kernel 4: GEMM + dual-sided fused epilogue ----------------
__global__ void __launch_bounds__(256, 1) epipass_kernel(const float* __restrict__ labels) {
    int bx = blockIdx.x, by = blockIdx.y;
    int tid = threadIdx.x;

    if (by > bx) {
        // zero-fill unused partial slots for deterministic full-sum reduce
        for (int t = tid; t < 128; t += 256) {
            #pragma unroll
            for (int k = 0; k < 3; k++) {
                g_pdr[k][bx][by * 128 + t] = 0.0f;
                g_pdc[k][by][bx * 128 + t] = 0.0f;
            }
        }
        return;
    }

    extern __shared__ char sm[];
    __shared__ float yr[128], yc[128];
    __shared__ float rp[3][2][128];
    __shared__ float cp[3][4][128];
    uint32_t sb = smem_u32(sm);
    int wid = tid >> 5, lane = tid & 31;
    int wm = wid & 3, wn = wid >> 2;

    for (int t = tid; t < 128; t += 256) {
        yr[t] = labels[(by * 128 + t) & (Bb - 1)];
        yc[t] = labels[(bx * 128 + t) & (Bb - 1)];
    }

    float c[2][8][4];
    gemm_tile_mma(sm, sb, by, bx, tid, wid, lane, c);   // has __syncthreads inside

    float inv_dz = 1.0f / ((1.0f - funflip(g_min_key)) + EPSV);
    float inv_dy = g_inv_dymax;
    bool diag = (by == bx);

    int tr = lane >> 2, tq = (lane & 3) * 2;
    float yi_[4];
    yi_[0] = yr[wm * 32 + tr];       yi_[1] = yr[wm * 32 + tr + 8];
    yi_[2] = yr[wm * 32 + tr + 16];  yi_[3] = yr[wm * 32 + tr + 24];

    float rden[4] = {0,0,0,0}, rs1[4] = {0,0,0,0}, rs2[4] = {0,0,0,0};

    #pragma unroll
    for (int in = 0; in < 8; in++) {
        int cl0 = wn * 64 + in * 8 + tq;
        float yj[2] = { yc[cl0], yc[cl0 + 1] };
        float cd[2] = {0,0}, c1[2] = {0,0}, c2[2] = {0,0};
        #pragma unroll
        for (int im = 0; im < 2; im++) {
            #pragma unroll
            for (int r = 0; r < 4; r++) {
                int rh = r >> 1, dl = r & 1;
                int rl = wm * 32 + im * 16 + rh * 8 + tr;
                float s  = c[im][in][r];
                float t  = s * INV_T;
                float es = __expf(t);
                float dy = yi_[im * 2 + rh] - yj[dl];
                float w  = __expf(-2.0f * dy * dy);
                float u  = fminf(fmaxf((1.0f - s) * inv_dz - fabsf(dy) * inv_dy, -1.0f), 1.0f);
                float wh = fmaf(w, u, 1.0f + fmaxf(-u, 0.0f));
                if (diag && (rl == cl0 + dl)) { es = 0.0f; wh = 0.0f; }
                int ri = im * 2 + rh;
                rden[ri] += es; rs1[ri] += wh; rs2[ri] = fmaf(wh * wh, t, rs2[ri]);
                cd[dl]   += es; c1[dl]  += wh; c2[dl]  = fmaf(wh * wh, t, c2[dl]);
            }
        }
        // column reduction: lanes sharing (lane&3) differ in bits 2..4
        #pragma unroll
        for (int off = 4; off <= 16; off <<= 1) {
            #pragma unroll
            for (int d = 0; d < 2; d++) {
                cd[d] += __shfl_xor_sync(0xffffffffu, cd[d], off);
                c1[d] += __shfl_xor_sync(0xffffffffu, c1[d], off);
                c2[d] += __shfl_xor_sync(0xffffffffu, c2[d], off);
            }
        }
        if (lane < 4) {
            int col = wn * 64 + in * 8 + lane * 2;
            cp[0][wm][col] = cd[0]; cp[0][wm][col + 1] = cd[1];
            cp[1][wm][col] = c1[0]; cp[1][wm][col + 1] = c1[1];
            cp[2][wm][col] = c2[0]; cp[2][wm][col + 1] = c2[1];
        }
    }

    // row reduction: lanes sharing tr differ in bits 0..1
    #pragma unroll
    for (int off = 1; off <= 2; off <<= 1) {
        #pragma unroll
        for (int ri = 0; ri < 4; ri++) {
            rden[ri] += __shfl_xor_sync(0xffffffffu, rden[ri], off);
            rs1[ri]  += __shfl_xor_sync(0xffffffffu, rs1[ri],  off);
            rs2[ri]  += __shfl_xor_sync(0xffffffffu, rs2[ri],  off);
        }
    }
    if ((lane & 3) == 0) {
        #pragma unroll
        for (int ri = 0; ri < 4; ri++) {
            int row = wm * 32 + (ri >> 1) * 16 + (ri & 1) * 8 + tr;
            rp[0][wn][row] = rden[ri];
            rp[1][wn][row] = rs1[ri];
            rp[2][wn][row] = rs2[ri];
        }
    }
    __syncthreads();

    if (tid < 128) {
        int row = tid, ig = by * 128 + row;
        #pragma unroll
        for (int k = 0; k < 3; k++)
            g_pdr[k][bx][ig] = rp[k][0][row] + rp[k][1][row];
    } else {
        int col = tid - 128, jg = bx * 128 + col;
        #pragma unroll
        for (int k = 0; k < 3; k++)
            g_pdc[k][by][jg] = diag ? 0.0f
                : (cp[k][0][col] + cp[k][1][col] + cp[k][2][col] + cp[k][3][col]);
    }
}

// ---------------- kernel 5: reduce partials per row ----------------
__global__ void rowred_kernel() {
    int i = blockIdx.x * blockDim.x + threadIdx.x;   // 4096 threads
    float d = 0.0f, a = 0.0f, b = 0.0f;
    #pragma unroll
    for (int s = 0; s < NT; s++) {
        d += g_pdr[0][s][i] + g_pdc[0][s][i];
        a += g_pdr[1][s][i] + g_pdc[1][s][i];
        b += g_pdr[2][s][i] + g_pdc[2][s][i];
    }
    float L = logf(d + EPSV);
    g_row[i] = (b - a * L) / (a + EPSV);
}

// ---------------- kernel 6: final mean ----------------
__global__ void final_kernel(float* __restrict__ out) {
    __shared__ float smem[32];
    int tid = threadIdx.x;
    float s = 0.0f;
    for (int i = tid; i < Nn; i += 1024) s += g_row[i];
    #pragma unroll
    for (int off = 16; off; off >>= 1) s += __shfl_xor_sync(0xffffffffu, s, off);
    int lane = tid & 31, w = tid >> 5;
    if (lane == 0) smem[w] = s;
    __syncthreads();
    if (tid == 0) {
        float t = 0.0f;
        #pragma unroll
        for (int x = 0; x < 32; x++) t += smem[x];
        out[0] = -(t / (float)Nn);
    }
}

// ---------------- launch ----------------
extern "C" void kernel_launch(void* const* d_in, const int* in_sizes, int n_in,
                              void* d_out, int out_size) {
    const float* feats  = (const float*)d_in[0];
    const float* labels = (const float*)d_in[1];
    float* out = (float*)d_out;

    cudaFuncSetAttribute(minpass_kernel, cudaFuncAttributeMaxDynamicSharedMemorySize, PANEL_BYTES);
    cudaFuncSetAttribute(epipass_kernel, cudaFuncAttributeMaxDynamicSharedMemorySize, PANEL_BYTES);

    labels_kernel<<<1, 1024>>>(labels);
    normalize_kernel<<<512, 256>>>(feats);
    dim3 g(NT, NT);
    minpass_kernel<<<g, 256, PANEL_BYTES>>>();
    epipass_kernel<<<g, 256, PANEL_BYTES>>>(labels);
    rowred_kernel<<<16, 256>>>();
    final_kernel<<<1, 1024>>>(out);
}

// round 6
// speedup vs baseline: 2.1725x; 1.1059x over previous
#include <cuda_runtime.h>
#include <cuda_bf16.h>
#include <math.h>
#include <stdint.h>

#define Nn   4096
#define Bb   2048
#define DIM  128
#define NT   32
#define NTILES 528
#define EPSV 1e-8f
#define INV_T 14.285714285714285714f   // 1/0.07

// ---------------- static device scratch ----------------
__device__ __nv_bfloat16 g_zh[Nn * DIM];          // 1 MB hi split
__device__ __nv_bfloat16 g_zl[Nn * DIM];          // 1 MB lo split
__device__ float         g_simu[NTILES * 16384];  // 34.6 MB upper-tri sim tiles
__device__ float         g_pdr[3][NT][Nn];        // row-side partials (slot = bx)
__device__ float         g_pdc[3][NT][Nn];        // col-side partials (slot = by)
__device__ float         g_row[Nn];
__device__ float         g_inv_dymax;
__device__ unsigned      g_min_key;

// panel layout in dynamic smem (bf16, 128 rows x 136 stride = 272 B/row)
#define PSTRIDE_B 272
#define OFF_AH 0
#define OFF_AL 34816
#define OFF_BH 69632
#define OFF_BL 104448
#define PANEL_BYTES 139264

__device__ __forceinline__ unsigned fflip(float f) {
    unsigned u = __float_as_uint(f);
    return (u & 0x80000000u) ? ~u : (u | 0x80000000u);
}
__device__ __forceinline__ float funflip(unsigned k) {
    return __uint_as_float((k & 0x80000000u) ? (k & 0x7FFFFFFFu) : ~k);
}
__device__ __forceinline__ uint32_t smem_u32(const void* p) {
    uint32_t a;
    asm("{ .reg .u64 t; cvta.to.shared.u64 t, %1; cvt.u32.u64 %0, t; }" : "=r"(a) : "l"(p));
    return a;
}
__device__ __forceinline__ void ldsm4(uint32_t& r0, uint32_t& r1, uint32_t& r2, uint32_t& r3, uint32_t a) {
    asm volatile("ldmatrix.sync.aligned.m8n8.x4.shared.b16 {%0,%1,%2,%3}, [%4];"
                 : "=r"(r0), "=r"(r1), "=r"(r2), "=r"(r3) : "r"(a));
}
__device__ __forceinline__ void mma16816(float* c, const uint32_t* a, const uint32_t* b) {
    asm volatile("mma.sync.aligned.m16n8k16.row.col.f32.bf16.bf16.f32 "
                 "{%0,%1,%2,%3},{%4,%5,%6,%7},{%8,%9},{%0,%1,%2,%3};"
                 : "+f"(c[0]), "+f"(c[1]), "+f"(c[2]), "+f"(c[3])
                 : "r"(a[0]), "r"(a[1]), "r"(a[2]), "r"(a[3]), "r"(b[0]), "r"(b[1]));
}
__device__ __forceinline__ int tile_index(int by, int bx) {
    return by * NT - (by * (by - 1)) / 2 + (bx - by);
}

// ---------------- kernel 1: labels min/max + init ----------------
__global__ void labels_kernel(const float* __restrict__ labels) {
    __shared__ float smn[32], smx[32];
    int tid = threadIdx.x;
    float mn = 1e30f, mx = -1e30f;
    for (int i = tid; i < Bb; i += 1024) {
        float v = labels[i];
        mn = fminf(mn, v); mx = fmaxf(mx, v);
    }
    #pragma unroll
    for (int off = 16; off; off >>= 1) {
        mn = fminf(mn, __shfl_xor_sync(0xffffffffu, mn, off));
        mx = fmaxf(mx, __shfl_xor_sync(0xffffffffu, mx, off));
    }
    int lane = tid & 31, w = tid >> 5;
    if (lane == 0) { smn[w] = mn; smx[w] = mx; }
    __syncthreads();
    if (tid == 0) {
        float a = smn[0], b = smx[0];
        for (int i = 1; i < 32; i++) { a = fminf(a, smn[i]); b = fmaxf(b, smx[i]); }
        g_inv_dymax = 1.0f / ((b - a) + EPSV);
        g_min_key   = 0xFFFFFFFFu;
    }
}

// ---------------- kernel 2: normalize + bf16 split ----------------
__global__ void normalize_kernel(const float* __restrict__ feats) {
    int gw   = (blockIdx.x * blockDim.x + threadIdx.x) >> 5;
    int lane = threadIdx.x & 31;
    if (gw >= Nn) return;
    int b = gw & (Bb - 1);
    int v = gw >> 11;
    const float* src = feats + ((size_t)b * 2 + v) * DIM;
    float4 x = *(const float4*)(src + lane * 4);
    float s = x.x * x.x + x.y * x.y + x.z * x.z + x.w * x.w;
    #pragma unroll
    for (int off = 16; off; off >>= 1) s += __shfl_xor_sync(0xffffffffu, s, off);
    float inv = 1.0f / fmaxf(sqrtf(s), 1e-12f);
    float f0 = x.x * inv, f1 = x.y * inv, f2 = x.z * inv, f3 = x.w * inv;
    __nv_bfloat16 h0 = __float2bfloat16(f0), h1 = __float2bfloat16(f1);
    __nv_bfloat16 h2 = __float2bfloat16(f2), h3 = __float2bfloat16(f3);
    __nv_bfloat16 l0 = __float2bfloat16(f0 - __bfloat162float(h0));
    __nv_bfloat16 l1 = __float2bfloat16(f1 - __bfloat162float(h1));
    __nv_bfloat16 l2 = __float2bfloat16(f2 - __bfloat162float(h2));
    __nv_bfloat16 l3 = __float2bfloat16(f3 - __bfloat162float(h3));
    size_t base = (size_t)gw * DIM + lane * 4;
    *(__nv_bfloat162*)(g_zh + base)     = __halves2bfloat162(h0, h1);
    *(__nv_bfloat162*)(g_zh + base + 2) = __halves2bfloat162(h2, h3);
    *(__nv_bfloat162*)(g_zl + base)     = __halves2bfloat162(l0, l1);
    *(__nv_bfloat162*)(g_zl + base + 2) = __halves2bfloat162(l2, l3);
}

// ---------------- kernel 3: GEMM upper tiles -> min + fp32 tile store -------
__global__ void __launch_bounds__(256, 1) simgen_kernel() {
    int bx = blockIdx.x, by = blockIdx.y;
    if (by > bx) return;
    extern __shared__ char sm[];
    __shared__ float wmin[8];
    uint32_t sb = smem_u32(sm);
    int tid = threadIdx.x, wid = tid >> 5, lane = tid & 31;
    int wm = wid & 3, wn = wid >> 2;

    // ---- load panels ----
    int r0 = by * 128, c0 = bx * 128;
    #pragma unroll
    for (int idx = tid; idx < 2048; idx += 256) {
        int row = idx >> 4, ch = idx & 15;
        size_t gA = (size_t)(r0 + row) * DIM + ch * 8;
        size_t gB = (size_t)(c0 + row) * DIM + ch * 8;
        uint32_t so = (uint32_t)row * PSTRIDE_B + ch * 16;
        *(uint4*)(sm + OFF_AH + so) = *(const uint4*)(g_zh + gA);
        *(uint4*)(sm + OFF_AL + so) = *(const uint4*)(g_zl + gA);
        *(uint4*)(sm + OFF_BH + so) = *(const uint4*)(g_zh + gB);
        *(uint4*)(sm + OFF_BL + so) = *(const uint4*)(g_zl + gB);
    }
    __syncthreads();

    float c[2][8][4];
    #pragma unroll
    for (int im = 0; im < 2; im++)
        #pragma unroll
        for (int in = 0; in < 8; in++)
            #pragma unroll
            for (int r = 0; r < 4; r++) c[im][in][r] = 0.0f;

    int a_row  = ((lane >> 3) & 1) * 8 + (lane & 7);
    int a_koff = (lane >> 4) * 8;
    int b_row  = ((lane >> 4) & 1) * 8 + (lane & 7);
    int b_koff = ((lane >> 3) & 1) * 8;

    #pragma unroll
    for (int kc = 0; kc < 8; kc++) {
        uint32_t ah[2][4], al[2][4], bh[8][2], bl[8][2];
        #pragma unroll
        for (int im = 0; im < 2; im++) {
            uint32_t off = (uint32_t)(wm * 32 + im * 16 + a_row) * PSTRIDE_B
                         + (kc * 16 + a_koff) * 2;
            ldsm4(ah[im][0], ah[im][1], ah[im][2], ah[im][3], sb + OFF_AH + off);
            ldsm4(al[im][0], al[im][1], al[im][2], al[im][3], sb + OFF_AL + off);
        }
        #pragma unroll
        for (int p = 0; p < 4; p++) {
            uint32_t off = (uint32_t)(wn * 64 + p * 16 + b_row) * PSTRIDE_B
                         + (kc * 16 + b_koff) * 2;
            ldsm4(bh[2*p][0], bh[2*p][1], bh[2*p+1][0], bh[2*p+1][1], sb + OFF_BH + off);
            ldsm4(bl[2*p][0], bl[2*p][1], bl[2*p+1][0], bl[2*p+1][1], sb + OFF_BL + off);
        }
        #pragma unroll
        for (int im = 0; im < 2; im++)
            #pragma unroll
            for (int in = 0; in < 8; in++) {
                mma16816(c[im][in], ah[im], bh[in]);
                mma16816(c[im][in], ah[im], bl[in]);
                mma16816(c[im][in], al[im], bh[in]);
            }
    }

    // ---- min reduction ----
    float mn = 1e30f;
    #pragma unroll
    for (int im = 0; im < 2; im++)
        #pragma unroll
        for (int in = 0; in < 8; in++)
            #pragma unroll
            for (int r = 0; r < 4; r++) mn = fminf(mn, c[im][in][r]);
    #pragma unroll
    for (int off = 16; off; off >>= 1) mn = fminf(mn, __shfl_xor_sync(0xffffffffu, mn, off));
    if (lane == 0) wmin[wid] = mn;
    __syncthreads();               // panels dead; wmin visible
    if (tid == 0) {
        float m = wmin[0];
        #pragma unroll
        for (int w = 1; w < 8; w++) m = fminf(m, wmin[w]);
        atomicMin(&g_min_key, fflip(m));
    }

    // ---- stage fp32 tile to smem (stride 132), then coalesced store ----
    float* stile = (float*)sm;     // 128*132*4 = 67.6 KB
    int tr = lane >> 2, tq = (lane & 3) * 2;
    #pragma unroll
    for (int im = 0; im < 2; im++)
        #pragma unroll
        for (int in = 0; in < 8; in++) {
            int rl = wm * 32 + im * 16 + tr;
            int cl = wn * 64 + in * 8 + tq;
            *(float2*)(stile + rl * 132 + cl)       = make_float2(c[im][in][0], c[im][in][1]);
            *(float2*)(stile + (rl + 8) * 132 + cl) = make_float2(c[im][in][2], c[im][in][3]);
        }
    __syncthreads();

    float* dst = g_simu + (size_t)tile_index(by, bx) * 16384;
    #pragma unroll
    for (int q = 0; q < 16; q++) {
        int e = q * 1024 + tid * 4;
        int row = e >> 7, col = e & 127;
        *(float4*)(dst + e) = *(const float4*)(stile + row * 132 + col);
    }
}

// ---------------- kernel 4: flat dual-sided epilogue over stored tiles ------
__global__ void __launch_bounds__(256) epiflat_kernel(const float* __restrict__ labels) {
    int bx = blockIdx.x, by = blockIdx.y;
    int tid = threadIdx.x;

    if (by > bx) {
        for (int t = tid; t < 128; t += 256) {
            #pragma unroll
            for (int k = 0; k < 3; k++) {
                g_pdr[k][bx][by * 128 + t] = 0.0f;
                g_pdc[k][by][bx * 128 + t] = 0.0f;
            }
        }
        return;
    }

    __shared__ float yr[128], yc[128];
    __shared__ float rowacc[3][128];
    __shared__ float colacc[8][3][128];
    int w = tid >> 5, l = tid & 31;

    for (int t = tid; t < 128; t += 256) {
        yr[t] = labels[(by * 128 + t) & (Bb - 1)];
        yc[t] = labels[(bx * 128 + t) & (Bb - 1)];
    }
    __syncthreads();

    float inv_dz = 1.0f / ((1.0f - funflip(g_min_key)) + EPSV);
    float inv_dy = g_inv_dymax;
    bool diag = (by == bx);
    const float4* tp = (const float4*)(g_simu + (size_t)tile_index(by, bx) * 16384);

    float cd[4] = {0,0,0,0}, c1[4] = {0,0,0,0}, c2[4] = {0,0,0,0};
    float yj[4];
    #pragma unroll
    for (int e = 0; e < 4; e++) yj[e] = yc[4 * l + e];

    #pragma unroll 4
    for (int it = 0; it < 16; it++) {
        int row = it * 8 + w;
        float4 s4 = tp[row * 32 + l];
        float se[4] = {s4.x, s4.y, s4.z, s4.w};
        float yi = yr[row];
        float rd = 0.0f, r1 = 0.0f, r2 = 0.0f;
        #pragma unroll
        for (int e = 0; e < 4; e++) {
            float s  = se[e];
            float t  = s * INV_T;
            float es = __expf(t);
            float dy = yi - yj[e];
            float wk = __expf(-2.0f * dy * dy);
            float u  = fminf(fmaxf((1.0f - s) * inv_dz - fabsf(dy) * inv_dy, -1.0f), 1.0f);
            float wh = fmaf(wk, u, 1.0f + fmaxf(-u, 0.0f));
            if (diag && (row == 4 * l + e)) { es = 0.0f; wh = 0.0f; }
            rd += es; r1 += wh; r2 = fmaf(wh * wh, t, r2);
            cd[e] += es; c1[e] += wh; c2[e] = fmaf(wh * wh, t, c2[e]);
        }
        #pragma unroll
        for (int off = 16; off; off >>= 1) {
            rd += __shfl_xor_sync(0xffffffffu, rd, off);
            r1 += __shfl_xor_sync(0xffffffffu, r1, off);
            r2 += __shfl_xor_sync(0xffffffffu, r2, off);
        }
        if (l == 0) { rowacc[0][row] = rd; rowacc[1][row] = r1; rowacc[2][row] = r2; }
    }

    #pragma unroll
    for (int e = 0; e < 4; e++) {
        colacc[w][0][4 * l + e] = cd[e];
        colacc[w][1][4 * l + e] = c1[e];
        colacc[w][2][4 * l + e] = c2[e];
    }
    __syncthreads();

    if (tid < 128) {
        int row = tid, ig = by * 128 + row;
        #pragma unroll
        for (int k = 0; k < 3; k++)
            g_pdr[k][bx][ig] = rowacc[k][row];
    } else {
        int col = tid - 128, jg = bx * 128 + col;
        #pragma unroll
        for (int k = 0; k < 3; k++) {
            float v = 0.0f;
            #pragma unroll
            for (int ww = 0; ww < 8; ww++) v += colacc[ww][k][col];
            g_pdc[k][by][jg] = diag ? 0.0f : v;
        }
    }
}

// ---------------- kernel 5: reduce partials per row ----------------
__global__ void rowred_kernel() {
    int i = blockIdx.x * blockDim.x + threadIdx.x;
    float d = 0.0f, a = 0.0f, b = 0.0f;
    #pragma unroll
    for (int s = 0; s < NT; s++) {
        d += g_pdr[0][s][i] + g_pdc[0][s][i];
        a += g_pdr[1][s][i] + g_pdc[1][s][i];
        b += g_pdr[2][s][i] + g_pdc[2][s][i];
    }
    float L = logf(d + EPSV);
    g_row[i] = (b - a * L) / (a + EPSV);
}

// ---------------- kernel 6: final mean ----------------
__global__ void final_kernel(float* __restrict__ out) {
    __shared__ float smem[32];
    int tid = threadIdx.x;
    float s = 0.0f;
    for (int i = tid; i < Nn; i += 1024) s += g_row[i];
    #pragma unroll
    for (int off = 16; off; off >>= 1) s += __shfl_xor_sync(0xffffffffu, s, off);
    int lane = tid & 31, w = tid >> 5;
    if (lane == 0) smem[w] = s;
    __syncthreads();
    if (tid == 0) {
        float t = 0.0f;
        #pragma unroll
        for (int x = 0; x < 32; x++) t += smem[x];
        out[0] = -(t / (float)Nn);
    }
}

// ---------------- launch ----------------
extern "C" void kernel_launch(void* const* d_in, const int* in_sizes, int n_in,
                              void* d_out, int out_size) {
    const float* feats  = (const float*)d_in[0];
    const float* labels = (const float*)d_in[1];
    float* out = (float*)d_out;

    cudaFuncSetAttribute(simgen_kernel, cudaFuncAttributeMaxDynamicSharedMemorySize, PANEL_BYTES);

    labels_kernel<<<1, 1024>>>(labels);
    normalize_kernel<<<512, 256>>>(feats);
    dim3 g(NT, NT);
    simgen_kernel<<<g, 256, PANEL_BYTES>>>();
    epiflat_kernel<<<g, 256>>>(labels);
    rowred_kernel<<<16, 256>>>();
    final_kernel<<<1, 1024>>>(out);
}

// round 7
// speedup vs baseline: 2.5268x; 1.1631x over previous
#include <cuda_runtime.h>
#include <cuda_bf16.h>
#include <math.h>
#include <stdint.h>

#define Nn   4096
#define Bb   2048
#define DIM  128
#define NT   32
#define NTILES 528
#define GRID 148
#define EPSV 1e-8f
#define INV_T 14.285714285714285714f   // 1/0.07

// ---------------- static device scratch ----------------
__device__ __nv_bfloat16 g_zh[Nn * DIM];          // 1 MB hi split
__device__ __nv_bfloat16 g_zl[Nn * DIM];          // 1 MB lo split
__device__ float         g_simu[(size_t)NTILES * 16384]; // 34.6 MB upper-tri tiles
__device__ float         g_pdr[3][NT][Nn];        // row-side partials (slot = bx)
__device__ float         g_pdc[3][NT][Nn];        // col-side partials (slot = by)
__device__ float         g_row[Nn];
__device__ float         g_inv_dymax;
__device__ unsigned      g_min_key;

// panel layout in dynamic smem (bf16, 128 rows x 136 stride = 272 B/row)
#define PSTRIDE_B 272
#define OFF_A_H   0
#define OFF_A_L   34816
#define OFF_B0_H  69632
#define OFF_B0_L  104448
#define OFF_B1_H  139264
#define OFF_B1_L  174080
#define PANEL_BYTES 208896

__device__ __forceinline__ unsigned fflip(float f) {
    unsigned u = __float_as_uint(f);
    return (u & 0x80000000u) ? ~u : (u | 0x80000000u);
}
__device__ __forceinline__ float funflip(unsigned k) {
    return __uint_as_float((k & 0x80000000u) ? (k & 0x7FFFFFFFu) : ~k);
}
__device__ __forceinline__ uint32_t smem_u32(const void* p) {
    uint32_t a;
    asm("{ .reg .u64 t; cvta.to.shared.u64 t, %1; cvt.u32.u64 %0, t; }" : "=r"(a) : "l"(p));
    return a;
}
__device__ __forceinline__ void cp16(uint32_t s, const void* g) {
    asm volatile("cp.async.cg.shared.global [%0], [%1], 16;" :: "r"(s), "l"(g));
}
__device__ __forceinline__ void cp_commit() {
    asm volatile("cp.async.commit_group;");
}
template <int N> __device__ __forceinline__ void cp_wait() {
    asm volatile("cp.async.wait_group %0;" :: "n"(N));
}
__device__ __forceinline__ void ldsm4(uint32_t& r0, uint32_t& r1, uint32_t& r2, uint32_t& r3, uint32_t a) {
    asm volatile("ldmatrix.sync.aligned.m8n8.x4.shared.b16 {%0,%1,%2,%3}, [%4];"
                 : "=r"(r0), "=r"(r1), "=r"(r2), "=r"(r3) : "r"(a));
}
__device__ __forceinline__ void mma16816(float* c, const uint32_t* a, const uint32_t* b) {
    asm volatile("mma.sync.aligned.m16n8k16.row.col.f32.bf16.bf16.f32 "
                 "{%0,%1,%2,%3},{%4,%5,%6,%7},{%8,%9},{%0,%1,%2,%3};"
                 : "+f"(c[0]), "+f"(c[1]), "+f"(c[2]), "+f"(c[3])
                 : "r"(a[0]), "r"(a[1]), "r"(a[2]), "r"(a[3]), "r"(b[0]), "r"(b[1]));
}

// ---------------- kernel 1: labels min/max + init ----------------
__global__ void labels_kernel(const float* __restrict__ labels) {
    __shared__ float smn[32], smx[32];
    int tid = threadIdx.x;
    float mn = 1e30f, mx = -1e30f;
    for (int i = tid; i < Bb; i += 1024) {
        float v = labels[i];
        mn = fminf(mn, v); mx = fmaxf(mx, v);
    }
    #pragma unroll
    for (int off = 16; off; off >>= 1) {
        mn = fminf(mn, __shfl_xor_sync(0xffffffffu, mn, off));
        mx = fmaxf(mx, __shfl_xor_sync(0xffffffffu, mx, off));
    }
    int lane = tid & 31, w = tid >> 5;
    if (lane == 0) { smn[w] = mn; smx[w] = mx; }
    __syncthreads();
    if (tid == 0) {
        float a = smn[0], b = smx[0];
        for (int i = 1; i < 32; i++) { a = fminf(a, smn[i]); b = fmaxf(b, smx[i]); }
        g_inv_dymax = 1.0f / ((b - a) + EPSV);
        g_min_key   = 0xFFFFFFFFu;
    }
}

// ---------------- kernel 2: normalize + bf16 split ----------------
__global__ void normalize_kernel(const float* __restrict__ feats) {
    int gw   = (blockIdx.x * blockDim.x + threadIdx.x) >> 5;
    int lane = threadIdx.x & 31;
    if (gw >= Nn) return;
    int b = gw & (Bb - 1);
    int v = gw >> 11;
    const float* src = feats + ((size_t)b * 2 + v) * DIM;
    float4 x = *(const float4*)(src + lane * 4);
    float s = x.x * x.x + x.y * x.y + x.z * x.z + x.w * x.w;
    #pragma unroll
    for (int off = 16; off; off >>= 1) s += __shfl_xor_sync(0xffffffffu, s, off);
    float inv = 1.0f / fmaxf(sqrtf(s), 1e-12f);
    float f0 = x.x * inv, f1 = x.y * inv, f2 = x.z * inv, f3 = x.w * inv;
    __nv_bfloat16 h0 = __float2bfloat16(f0), h1 = __float2bfloat16(f1);
    __nv_bfloat16 h2 = __float2bfloat16(f2), h3 = __float2bfloat16(f3);
    __nv_bfloat16 l0 = __float2bfloat16(f0 - __bfloat162float(h0));
    __nv_bfloat16 l1 = __float2bfloat16(f1 - __bfloat162float(h1));
    __nv_bfloat16 l2 = __float2bfloat16(f2 - __bfloat162float(h2));
    __nv_bfloat16 l3 = __float2bfloat16(f3 - __bfloat162float(h3));
    size_t base = (size_t)gw * DIM + lane * 4;
    *(__nv_bfloat162*)(g_zh + base)     = __halves2bfloat162(h0, h1);
    *(__nv_bfloat162*)(g_zh + base + 2) = __halves2bfloat162(h2, h3);
    *(__nv_bfloat162*)(g_zl + base)     = __halves2bfloat162(l0, l1);
    *(__nv_bfloat162*)(g_zl + base + 2) = __halves2bfloat162(l2, l3);
}

// ---- cp.async panel loaders (H+L pair for one 128-row block) ----
__device__ __forceinline__ void load_panels(uint32_t sb, uint32_t offH, uint32_t offL,
                                            int blk, int tid) {
    #pragma unroll
    for (int c = tid; c < 2048; c += 256) {
        int row = c >> 4, ch = c & 15;
        uint32_t so = (uint32_t)row * PSTRIDE_B + ch * 16;
        size_t go = (size_t)(blk * 128 + row) * DIM + ch * 8;
        cp16(sb + offH + so, g_zh + go);
        cp16(sb + offL + so, g_zl + go);
    }
}

// ---- MMA on current buffers: c += Ah*BhT + Ah*BlT + Al*BhT ----
__device__ __forceinline__ void tile_mma(uint32_t sb, uint32_t offBH, uint32_t offBL,
                                         int wm, int wn, int lane, float c[2][8][4]) {
    #pragma unroll
    for (int im = 0; im < 2; im++)
        #pragma unroll
        for (int in = 0; in < 8; in++)
            #pragma unroll
            for (int r = 0; r < 4; r++) c[im][in][r] = 0.0f;

    int a_row  = ((lane >> 3) & 1) * 8 + (lane & 7);
    int a_koff = (lane >> 4) * 8;
    int b_row  = ((lane >> 4) & 1) * 8 + (lane & 7);
    int b_koff = ((lane >> 3) & 1) * 8;

    #pragma unroll
    for (int kc = 0; kc < 8; kc++) {
        uint32_t ah[2][4], al[2][4], bh[8][2], bl[8][2];
        #pragma unroll
        for (int im = 0; im < 2; im++) {
            uint32_t off = (uint32_t)(wm * 32 + im * 16 + a_row) * PSTRIDE_B
                         + (kc * 16 + a_koff) * 2;
            ldsm4(ah[im][0], ah[im][1], ah[im][2], ah[im][3], sb + OFF_A_H + off);
            ldsm4(al[im][0], al[im][1], al[im][2], al[im][3], sb + OFF_A_L + off);
        }
        #pragma unroll
        for (int p = 0; p < 4; p++) {
            uint32_t off = (uint32_t)(wn * 64 + p * 16 + b_row) * PSTRIDE_B
                         + (kc * 16 + b_koff) * 2;
            ldsm4(bh[2*p][0], bh[2*p][1], bh[2*p+1][0], bh[2*p+1][1], sb + offBH + off);
            ldsm4(bl[2*p][0], bl[2*p][1], bl[2*p+1][0], bl[2*p+1][1], sb + offBL + off);
        }
        #pragma unroll
        for (int im = 0; im < 2; im++)
            #pragma unroll
            for (int in = 0; in < 8; in++) {
                mma16816(c[im][in], ah[im], bh[in]);
                mma16816(c[im][in], ah[im], bl[in]);
                mma16816(c[im][in], al[im], bh[in]);
            }
    }
}

// ---------------- kernel 3: persistent pipelined GEMM ----------------
__global__ void __launch_bounds__(256, 1) simgen_kernel() {
    extern __shared__ char sm[];
    __shared__ float wmin[8];
    uint32_t sb = smem_u32(sm);
    int tid = threadIdx.x, wid = tid >> 5, lane = tid & 31;
    int wm = wid & 3, wn = wid >> 2;
    int tr = lane >> 2, tq = (lane & 3) * 2;

    int k = blockIdx.x;
    int ts = (k * NTILES) / GRID;
    int te = ((k + 1) * NTILES) / GRID;

    // decode (by, bx) of tile ts
    int by = 0, off = 0;
    while (ts >= off + (NT - by)) { off += (NT - by); by++; }
    int bx = by + (ts - off);

    float mymin = 1e30f;
    int t = ts;
    while (t < te) {
        int nb = NT - bx;                 // tiles left in this row
        if (nb > te - t) nb = te - t;     // tiles left in our range

        // load A(by) + first B(bx) as one group (prior MMA finished: trailing sync)
        load_panels(sb, OFF_A_H, OFF_A_L, by, tid);
        load_panels(sb, OFF_B0_H, OFF_B0_L, bx, tid);
        cp_commit();

        for (int j = 0; j < nb; j++) {
            int cbx = bx + j;
            uint32_t bH = (j & 1) ? OFF_B1_H : OFF_B0_H;
            uint32_t bL = (j & 1) ? OFF_B1_L : OFF_B0_L;
            bool pf = (j + 1 < nb);
            if (pf) {
                load_panels(sb, (j & 1) ? OFF_B0_H : OFF_B1_H,
                                (j & 1) ? OFF_B0_L : OFF_B1_L, cbx + 1, tid);
                cp_commit();
                cp_wait<1>();
            } else {
                cp_wait<0>();
            }
            __syncthreads();

            float c[2][8][4];
            tile_mma(sb, bH, bL, wm, wn, lane, c);

            // fragment min + direct store (tile-contiguous 128x128 fp32)
            float* dst = g_simu + (size_t)(t + j) * 16384;
            #pragma unroll
            for (int im = 0; im < 2; im++)
                #pragma unroll
                for (int in = 0; in < 8; in++) {
                    int rl = wm * 32 + im * 16 + tr;
                    int cl = wn * 64 + in * 8 + tq;
                    float2 v0 = make_float2(c[im][in][0], c[im][in][1]);
                    float2 v1 = make_float2(c[im][in][2], c[im][in][3]);
                    *(float2*)(dst + rl * 128 + cl)       = v0;
                    *(float2*)(dst + (rl + 8) * 128 + cl) = v1;
                    mymin = fminf(mymin, fminf(fminf(v0.x, v0.y), fminf(v1.x, v1.y)));
                }
            __syncthreads();   // all warps done with this buffer before overwrite
        }
        t += nb;
        bx += nb;
        if (bx >= NT) { by++; bx = by; }
    }

    // per-CTA min -> global
    #pragma unroll
    for (int o = 16; o; o >>= 1) mymin = fminf(mymin, __shfl_xor_sync(0xffffffffu, mymin, o));
    if (lane == 0) wmin[wid] = mymin;
    __syncthreads();
    if (tid == 0) {
        float m = wmin[0];
        #pragma unroll
        for (int w = 1; w < 8; w++) m = fminf(m, wmin[w]);
        atomicMin(&g_min_key, fflip(m));
    }
}

// ---------------- kernel 4: flat dual-sided epilogue (1 CTA per tile) -------
__global__ void __launch_bounds__(512) epiflat_kernel(const float* __restrict__ labels) {
    __shared__ float yr[128], yc[128];
    __shared__ float rowacc[3][128];
    __shared__ float colacc[16][3][128];
    int tid = threadIdx.x, w = tid >> 5, l = tid & 31;

    // decode tile
    int t = blockIdx.x;
    int by = 0, off = 0;
    while (t >= off + (NT - by)) { off += (NT - by); by++; }
    int bx = by + (t - off);
    bool diag = (by == bx);

    for (int i = tid; i < 128; i += 512) {
        yr[i] = labels[(by * 128 + i) & (Bb - 1)];
        yc[i] = labels[(bx * 128 + i) & (Bb - 1)];
    }
    __syncthreads();

    float inv_dz = 1.0f / ((1.0f - funflip(g_min_key)) + EPSV);
    float inv_dy = g_inv_dymax;
    const float4* tp = (const float4*)(g_simu + (size_t)t * 16384);

    float cd[4] = {0,0,0,0}, c1[4] = {0,0,0,0}, c2[4] = {0,0,0,0};
    float yj[4];
    #pragma unroll
    for (int e = 0; e < 4; e++) yj[e] = yc[4 * l + e];

    #pragma unroll
    for (int it = 0; it < 8; it++) {
        int row = it * 16 + w;
        float4 s4 = tp[row * 32 + l];
        float se[4] = {s4.x, s4.y, s4.z, s4.w};
        float yi = yr[row];
        float rd = 0.0f, r1 = 0.0f, r2 = 0.0f;
        #pragma unroll
        for (int e = 0; e < 4; e++) {
            float s  = se[e];
            float tt = s * INV_T;
            float es = __expf(tt);
            float dy = yi - yj[e];
            float wk = __expf(-2.0f * dy * dy);
            float u  = fminf(fmaxf((1.0f - s) * inv_dz - fabsf(dy) * inv_dy, -1.0f), 1.0f);
            float wh = fmaf(wk, u, 1.0f + fmaxf(-u, 0.0f));
            if (diag && (row == 4 * l + e)) { es = 0.0f; wh = 0.0f; }
            rd += es; r1 += wh; r2 = fmaf(wh * wh, tt, r2);
            cd[e] += es; c1[e] += wh; c2[e] = fmaf(wh * wh, tt, c2[e]);
        }
        #pragma unroll
        for (int o = 16; o; o >>= 1) {
            rd += __shfl_xor_sync(0xffffffffu, rd, o);
            r1 += __shfl_xor_sync(0xffffffffu, r1, o);
            r2 += __shfl_xor_sync(0xffffffffu, r2, o);
        }
        if (l == 0) { rowacc[0][row] = rd; rowacc[1][row] = r1; rowacc[2][row] = r2; }
    }

    #pragma unroll
    for (int e = 0; e < 4; e++) {
        colacc[w][0][4 * l + e] = cd[e];
        colacc[w][1][4 * l + e] = c1[e];
        colacc[w][2][4 * l + e] = c2[e];
    }
    __syncthreads();

    if (tid < 128) {
        int row = tid, ig = by * 128 + row;
        #pragma unroll
        for (int k = 0; k < 3; k++)
            g_pdr[k][bx][ig] = rowacc[k][row];
    } else if (tid < 256) {
        int col = tid - 128, jg = bx * 128 + col;
        #pragma unroll
        for (int k = 0; k < 3; k++) {
            float v = 0.0f;
            #pragma unroll
            for (int ww = 0; ww < 16; ww++) v += colacc[ww][k][col];
            g_pdc[k][by][jg] = diag ? 0.0f : v;
        }
    }
}

// ---------------- kernel 5: reduce valid partial slots per row --------------
__global__ void rowred_kernel() {
    int i = blockIdx.x * blockDim.x + threadIdx.x;
    int p = i >> 7;
    float d = 0.0f, a = 0.0f, b = 0.0f;
    for (int s = p; s < NT; s++) {        // row-side: tiles (p, s), s >= p
        d += g_pdr[0][s][i];
        a += g_pdr[1][s][i];
        b += g_pdr[2][s][i];
    }
    for (int s = 0; s <= p; s++) {        // col-side: tiles (s, p), s <= p (diag slot = 0)
        d += g_pdc[0][s][i];
        a += g_pdc[1][s][i];
        b += g_pdc[2][s][i];
    }
    float L = logf(d + EPSV);
    g_row[i] = (b - a * L) / (a + EPSV);
}

// ---------------- kernel 6: final mean ----------------
__global__ void final_kernel(float* __restrict__ out) {
    __shared__ float smem[32];
    int tid = threadIdx.x;
    float s = 0.0f;
    for (int i = tid; i < Nn; i += 1024) s += g_row[i];
    #pragma unroll
    for (int off = 16; off; off >>= 1) s += __shfl_xor_sync(0xffffffffu, s, off);
    int lane = tid & 31, w = tid >> 5;
    if (lane == 0) smem[w] = s;
    __syncthreads();
    if (tid == 0) {
        float t = 0.0f;
        #pragma unroll
        for (int x = 0; x < 32; x++) t += smem[x];
        out[0] = -(t / (float)Nn);
    }
}

// ---------------- launch ----------------
extern "C" void kernel_launch(void* const* d_in, const int* in_sizes, int n_in,
                              void* d_out, int out_size) {
    const float* feats  = (const float*)d_in[0];
    const float* labels = (const float*)d_in[1];
    float* out = (float*)d_out;

    cudaFuncSetAttribute(simgen_kernel, cudaFuncAttributeMaxDynamicSharedMemorySize, PANEL_BYTES);

    labels_kernel<<<1, 1024>>>(labels);
    normalize_kernel<<<512, 256>>>(feats);
    simgen_kernel<<<GRID, 256, PANEL_BYTES>>>();
    epiflat_kernel<<<NTILES, 512>>>(labels);
    rowred_kernel<<<16, 256>>>();
    final_kernel<<<1, 1024>>>(out);
}